// round 4
// baseline (speedup 1.0000x reference)
#include <cuda_runtime.h>

typedef unsigned long long u64;

#define Dd   256
#define Hh   4
#define HDh  64
#define Ss   64
#define BM   64
#define TBS  258   // tbuf row stride (floats)
#define ASTR 36    // A staging row stride
#define BSTR 132   // B staging row stride
#define KVSTR 68   // key/val staging row stride
#define SIMSTR 66  // sim buffer row stride

// smem float offsets (BM=64 layout, 114,944 B -> 2 CTAs/SM)
#define OFF_TBUF 0                       // 64*258 = 16512
#define OFF_AS   16512                   // 64*36  = 2304
#define OFF_BS   (16512+2304)            // 32*132 = 4224 ; end 23040
#define OFF_SIM  16512                   // 64*66 = 4224, overlaps As+Bs (attention phase only)
#define OFF_KV   23040                   // 64*68 = 4352 ; end 27392
#define OFF_RED  23040                   // 64*16 = 1024, overlaps kv (phase A only)
#define OFF_CST  27392                   // 1024 : bq(256) bg(256) bo(256) bc1(128) wc2(128)
#define OFF_GACC (OFF_CST+1024)          // 28416
#define OFF_CACC (OFF_GACC+64)
#define OFF_A    (OFF_CACC+64)
#define OFF_B2   (OFF_A+64)
#define OFF_RQ   (OFF_B2+64)
#define SMEM_FLOATS (OFF_RQ+64)          // 28736
#define SMEM_BYTES (SMEM_FLOATS*4)       // 114944

// normalized, transposed keys: [tier][h][d*S + s]
__device__ float g_knT[2][Hh][HDh*Ss];

__global__ void prep_keys(const float* __restrict__ fk, const float* __restrict__ dk) {
    int t = threadIdx.x;          // 256 threads = (h,s)
    int h = t / Ss, s = t % Ss;
    const float* srcs[2] = { fk, dk };
    for (int tier = 0; tier < 2; tier++) {
        const float* src = srcs[tier] + (h * Ss + s) * HDh;
        float ssum = 0.f;
        for (int d2 = 0; d2 < HDh; d2++) { float v = src[d2]; ssum += v * v; }
        float r = 1.0f / (sqrtf(ssum) + 1e-8f);
        for (int d2 = 0; d2 < HDh; d2++)
            g_knT[tier][h][d2 * Ss + s] = src[d2] * r;
    }
}

__device__ __forceinline__ u64 pk2(float v) {
    u64 r; asm("mov.b64 %0, {%1,%2};" : "=l"(r) : "f"(v), "f"(v)); return r;
}
__device__ __forceinline__ void fma2(u64& acc, u64 a, u64 b) {
    asm("fma.rn.f32x2 %0, %1, %2, %0;" : "+l"(acc) : "l"(a), "l"(b));
}
__device__ __forceinline__ float2 unp(u64 v) {
    float2 f; asm("mov.b64 {%0,%1}, %2;" : "=f"(f.x), "=f"(f.y) : "l"(v)); return f;
}

// C[64 x 128] = A[64 x 256] @ W[n0..n0+127, 0..255]^T ; acc = 4x4 f32x2 per thread
__device__ __forceinline__ void gemm_256xN(
    const float* __restrict__ Ag, const float* __restrict__ W, int n0,
    float* As, float* Bs, u64 acc[4][4], int tid, int tx, int ty)
{
    #pragma unroll
    for (int i = 0; i < 4; i++)
        #pragma unroll
        for (int j = 0; j < 4; j++) acc[i][j] = 0ull;

    for (int kt = 0; kt < 8; kt++) {
        const int k0 = kt * 32;
        #pragma unroll
        for (int r = 0; r < 2; r++) {          // stage A tile 64x32 (row-major)
            int lin = tid + r * 256;
            int m = lin >> 3, q = lin & 7;
            float4 v = *(const float4*)(Ag + m * Dd + k0 + q * 4);
            *(float4*)(As + m * ASTR + q * 4) = v;
        }
        #pragma unroll
        for (int r = 0; r < 4; r++) {          // stage B tile transposed: Bs[k][n] = W[n0+n][k0+k]
            int lin = tid + r * 256;
            int n = lin >> 3, q = lin & 7;
            float4 v = *(const float4*)(W + (n0 + n) * Dd + k0 + q * 4);
            Bs[(q * 4 + 0) * BSTR + n] = v.x;
            Bs[(q * 4 + 1) * BSTR + n] = v.y;
            Bs[(q * 4 + 2) * BSTR + n] = v.z;
            Bs[(q * 4 + 3) * BSTR + n] = v.w;
        }
        __syncthreads();
        #pragma unroll
        for (int kk = 0; kk < 32; kk += 4) {
            float4 a4[4];
            #pragma unroll
            for (int i = 0; i < 4; i++)
                a4[i] = *(const float4*)(As + (ty * 4 + i) * ASTR + kk);
            #pragma unroll
            for (int u = 0; u < 4; u++) {
                const float* brow = Bs + (kk + u) * BSTR + tx * 8;
                u64 b0 = *(const u64*)(brow + 0);
                u64 b1 = *(const u64*)(brow + 2);
                u64 b2 = *(const u64*)(brow + 4);
                u64 b3 = *(const u64*)(brow + 6);
                #pragma unroll
                for (int i = 0; i < 4; i++) {
                    float av = (u == 0) ? a4[i].x : (u == 1) ? a4[i].y : (u == 2) ? a4[i].z : a4[i].w;
                    u64 aa = pk2(av);
                    fma2(acc[i][0], aa, b0);
                    fma2(acc[i][1], aa, b1);
                    fma2(acc[i][2], aa, b2);
                    fma2(acc[i][3], aa, b3);
                }
            }
        }
        __syncthreads();
    }
}

// C[64 x 64] (+)= A[64 rows, cols acb..acb+63 of Asm] @ kvS[64 x 64]; acc = 4x2 f32x2
__device__ __forceinline__ void gemm_attn(
    const float* __restrict__ Asm, int astride, int acb,
    const float* __restrict__ kvS, u64 acc[4][2], int tx, int ty, bool zero)
{
    if (zero) {
        #pragma unroll
        for (int i = 0; i < 4; i++) { acc[i][0] = 0ull; acc[i][1] = 0ull; }
    }
    #pragma unroll 8
    for (int kk = 0; kk < 64; kk += 2) {
        float2 a2[4];
        #pragma unroll
        for (int i = 0; i < 4; i++)
            a2[i] = *(const float2*)(Asm + (ty * 4 + i) * astride + acb + kk);
        #pragma unroll
        for (int u = 0; u < 2; u++) {
            const float* brow = kvS + (kk + u) * KVSTR + tx * 4;
            u64 b0 = *(const u64*)(brow);
            u64 b1 = *(const u64*)(brow + 2);
            #pragma unroll
            for (int i = 0; i < 4; i++) {
                u64 aa = pk2(u ? a2[i].y : a2[i].x);
                fma2(acc[i][0], aa, b0);
                fma2(acc[i][1], aa, b1);
            }
        }
    }
}

__device__ __forceinline__ void stage_kv(float* kv, const float* __restrict__ src, int tid) {
    #pragma unroll
    for (int r = 0; r < 4; r++) {
        int lin = tid + r * 256;
        int row = lin >> 4, q = lin & 15;
        float4 v = *(const float4*)(src + row * 64 + q * 4);
        *(float4*)(kv + row * KVSTR + q * 4) = v;
    }
}

__device__ __forceinline__ void softmax_row(float* row, float scale) {
    float mx = -1e30f;
    for (int s2 = 0; s2 < 64; s2++) mx = fmaxf(mx, row[s2]);
    float sum = 0.f;
    for (int s2 = 0; s2 < 64; s2++) { float e = __expf(row[s2] - mx); row[s2] = e; sum += e; }
    float inv = scale / sum;
    for (int s2 = 0; s2 < 64; s2++) row[s2] *= inv;
}

__global__ void __launch_bounds__(256, 2) miras_main(
    const float* __restrict__ query, const float* __restrict__ context,
    const float* __restrict__ fvals, const float* __restrict__ dvals,
    const float* __restrict__ Wq, const float* __restrict__ bq,
    const float* __restrict__ Wg, const float* __restrict__ bg,
    const float* __restrict__ Wc1, const float* __restrict__ bc1,
    const float* __restrict__ Wc2, const float* __restrict__ bc2,
    const float* __restrict__ Wo, const float* __restrict__ bo,
    const float* __restrict__ mixl,
    float* __restrict__ out)
{
    extern __shared__ float sm[];
    float* tbuf = sm + OFF_TBUF;
    float* As   = sm + OFF_AS;
    float* Bs   = sm + OFF_BS;
    float* simb = sm + OFF_SIM;
    float* kv   = sm + OFF_KV;
    float* cst  = sm + OFF_CST;
    float* red  = sm + OFF_RED;
    float* gaccS = sm + OFF_GACC;
    float* caccS = sm + OFF_CACC;
    float* aS   = sm + OFF_A;
    float* b2S  = sm + OFF_B2;
    float* rqS  = sm + OFF_RQ;

    const int tid = threadIdx.x;
    const int tx = tid & 15, ty = tid >> 4;
    const int m0 = blockIdx.x * BM;

    // load small constants into smem
    cst[tid]       = bq[tid];
    cst[256 + tid] = bg[tid];
    cst[512 + tid] = bo[tid];
    if (tid < 128) { cst[768 + tid] = bc1[tid]; cst[896 + tid] = Wc2[tid]; }
    const float mix_logit = mixl[0];
    const float bc2v = bc2[0];
    __syncthreads();

    u64 acc[4][4];

    // ---------- Phase A: gate (Wg) + conf (Wc1) from context ----------
    float gpart[4];
    #pragma unroll
    for (int i = 0; i < 4; i++) gpart[i] = 0.f;

    for (int np = 0; np < 2; np++) {
        gemm_256xN(context + (size_t)m0 * Dd, Wg, np * 128, As, Bs, acc, tid, tx, ty);
        #pragma unroll
        for (int i = 0; i < 4; i++) {
            float s = 0.f;
            #pragma unroll
            for (int j = 0; j < 4; j++) {
                float2 v = unp(acc[i][j]);
                int n = np * 128 + tx * 8 + j * 2;
                s += tanhf(v.x + cst[256 + n]) + tanhf(v.y + cst[256 + n + 1]);
            }
            gpart[i] += s;
        }
    }

    gemm_256xN(context + (size_t)m0 * Dd, Wc1, 0, As, Bs, acc, tid, tx, ty);
    float cpart[4];
    #pragma unroll
    for (int i = 0; i < 4; i++) {
        float s = 0.f;
        #pragma unroll
        for (int j = 0; j < 4; j++) {
            float2 v = unp(acc[i][j]);
            int n = tx * 8 + j * 2;
            s += tanhf(v.x + cst[768 + n]) * cst[896 + n]
               + tanhf(v.y + cst[768 + n + 1]) * cst[896 + n + 1];
        }
        cpart[i] = s;
    }

    // deterministic reductions (red overlaps kv region; kv not used until phase C)
    #pragma unroll
    for (int i = 0; i < 4; i++) red[(ty * 4 + i) * 16 + tx] = gpart[i];
    __syncthreads();
    if (tid < 64) {
        float s = 0.f;
        for (int t16 = 0; t16 < 16; t16++) s += red[tid * 16 + t16];
        gaccS[tid] = s;
    }
    __syncthreads();
    #pragma unroll
    for (int i = 0; i < 4; i++) red[(ty * 4 + i) * 16 + tx] = cpart[i];
    __syncthreads();
    if (tid < 64) {
        float s = 0.f;
        for (int t16 = 0; t16 < 16; t16++) s += red[tid * 16 + t16];
        caccS[tid] = s;
        float gate = gaccS[tid] * (1.0f / 256.0f);
        float mixv = 1.0f / (1.0f + __expf(-(mix_logit + gate)));
        float conf = 1.0f / (1.0f + __expf(-(s + bc2v)));
        aS[tid] = mixv * conf;
        b2S[tid] = (1.0f - mixv) * conf;
    }
    __syncthreads();

    // ---------- Phase B: Q = query @ Wq^T + bq -> tbuf ----------
    for (int np = 0; np < 2; np++) {
        gemm_256xN(query + (size_t)m0 * Dd, Wq, np * 128, As, Bs, acc, tid, tx, ty);
        #pragma unroll
        for (int i = 0; i < 4; i++) {
            int row = ty * 4 + i;
            #pragma unroll
            for (int j = 0; j < 4; j++) {
                float2 v = unp(acc[i][j]);
                int n = np * 128 + tx * 8 + j * 2;
                tbuf[row * TBS + n]     = v.x + cst[n];
                tbuf[row * TBS + n + 1] = v.y + cst[n + 1];
            }
        }
        __syncthreads();
    }

    // ---------- Phase C: dual-tier cosine attention, in-place t over Q ----------
    u64 accS[4][2], accT[4][2];
    for (int h = 0; h < Hh; h++) {
        stage_kv(kv, &g_knT[0][h][0], tid);
        if (tid < 64) {
            const float* qr = tbuf + tid * TBS + h * 64;
            float ssum = 0.f;
            for (int d2 = 0; d2 < 64; d2++) { float v = qr[d2]; ssum += v * v; }
            rqS[tid] = 1.0f / (sqrtf(ssum) + 1e-8f);
        }
        __syncthreads();

        // sim fast = Q_h @ knT_f, scaled by 1/(||q||+eps)
        gemm_attn(tbuf, TBS, h * 64, kv, accS, tx, ty, true);
        #pragma unroll
        for (int i = 0; i < 4; i++) {
            float r = rqS[ty * 4 + i];
            float2 v0 = unp(accS[i][0]), v1 = unp(accS[i][1]);
            float* srow = simb + (ty * 4 + i) * SIMSTR + tx * 4;
            srow[0] = v0.x * r; srow[1] = v0.y * r; srow[2] = v1.x * r; srow[3] = v1.y * r;
        }
        __syncthreads();

        stage_kv(kv, fvals + h * Ss * HDh, tid);
        if (tid < 64) softmax_row(simb + tid * SIMSTR, aS[tid]);   // attnF * conf*mix
        __syncthreads();

        gemm_attn(simb, SIMSTR, 0, kv, accT, tx, ty, true);         // t += attnF' @ fvals
        __syncthreads();

        stage_kv(kv, &g_knT[1][h][0], tid);
        __syncthreads();

        gemm_attn(tbuf, TBS, h * 64, kv, accS, tx, ty, true);       // sim deep
        #pragma unroll
        for (int i = 0; i < 4; i++) {
            float r = rqS[ty * 4 + i];
            float2 v0 = unp(accS[i][0]), v1 = unp(accS[i][1]);
            float* srow = simb + (ty * 4 + i) * SIMSTR + tx * 4;
            srow[0] = v0.x * r; srow[1] = v0.y * r; srow[2] = v1.x * r; srow[3] = v1.y * r;
        }
        __syncthreads();

        stage_kv(kv, dvals + h * Ss * HDh, tid);
        if (tid < 64) softmax_row(simb + tid * SIMSTR, b2S[tid]);  // attnD * conf*(1-mix)
        __syncthreads();

        gemm_attn(simb, SIMSTR, 0, kv, accT, tx, ty, false);        // t += attnD' @ dvals

        #pragma unroll
        for (int i = 0; i < 4; i++) {                               // overwrite Q_h with t_h
            float2 v0 = unp(accT[i][0]), v1 = unp(accT[i][1]);
            float* trow = tbuf + (ty * 4 + i) * TBS + h * 64 + tx * 4;
            trow[0] = v0.x; trow[1] = v0.y; trow[2] = v1.x; trow[3] = v1.y;
        }
        __syncthreads();
    }

    // ---------- Phase D: out = t @ Wo^T + bo ----------
    for (int np = 0; np < 2; np++) {
        #pragma unroll
        for (int i = 0; i < 4; i++)
            #pragma unroll
            for (int j = 0; j < 4; j++) acc[i][j] = 0ull;

        for (int kt = 0; kt < 8; kt++) {
            const int k0 = kt * 32;
            #pragma unroll
            for (int r = 0; r < 4; r++) {
                int lin = tid + r * 256;
                int n = lin >> 3, q = lin & 7;
                float4 v = *(const float4*)(Wo + (np * 128 + n) * Dd + k0 + q * 4);
                Bs[(q * 4 + 0) * BSTR + n] = v.x;
                Bs[(q * 4 + 1) * BSTR + n] = v.y;
                Bs[(q * 4 + 2) * BSTR + n] = v.z;
                Bs[(q * 4 + 3) * BSTR + n] = v.w;
            }
            __syncthreads();
            #pragma unroll
            for (int kk = 0; kk < 32; kk += 2) {
                float2 a2[4];
                #pragma unroll
                for (int i = 0; i < 4; i++)
                    a2[i] = *(const float2*)(tbuf + (ty * 4 + i) * TBS + k0 + kk);
                #pragma unroll
                for (int u = 0; u < 2; u++) {
                    const float* brow = Bs + (kk + u) * BSTR + tx * 8;
                    u64 b0 = *(const u64*)(brow + 0);
                    u64 b1 = *(const u64*)(brow + 2);
                    u64 b2 = *(const u64*)(brow + 4);
                    u64 b3 = *(const u64*)(brow + 6);
                    #pragma unroll
                    for (int i = 0; i < 4; i++) {
                        u64 aa = pk2(u ? a2[i].y : a2[i].x);
                        fma2(acc[i][0], aa, b0);
                        fma2(acc[i][1], aa, b1);
                        fma2(acc[i][2], aa, b2);
                        fma2(acc[i][3], aa, b3);
                    }
                }
            }
            __syncthreads();
        }
        #pragma unroll
        for (int i = 0; i < 4; i++) {
            int row = m0 + ty * 4 + i;
            float2 v0 = unp(acc[i][0]), v1 = unp(acc[i][1]);
            float2 v2 = unp(acc[i][2]), v3 = unp(acc[i][3]);
            int n = np * 128 + tx * 8;
            float4 o0 = make_float4(v0.x + cst[512 + n],     v0.y + cst[512 + n + 1],
                                    v1.x + cst[512 + n + 2], v1.y + cst[512 + n + 3]);
            float4 o1 = make_float4(v2.x + cst[512 + n + 4], v2.y + cst[512 + n + 5],
                                    v3.x + cst[512 + n + 6], v3.y + cst[512 + n + 7]);
            *(float4*)(out + (size_t)row * Dd + n)     = o0;
            *(float4*)(out + (size_t)row * Dd + n + 4) = o1;
        }
    }
}

extern "C" void kernel_launch(void* const* d_in, const int* in_sizes, int n_in,
                              void* d_out, int out_size) {
    (void)in_sizes; (void)n_in; (void)out_size;
    const float* query   = (const float*)d_in[0];
    const float* context = (const float*)d_in[1];
    const float* fk  = (const float*)d_in[2];
    const float* fv  = (const float*)d_in[3];
    const float* dk  = (const float*)d_in[4];
    const float* dv  = (const float*)d_in[5];
    const float* Wq  = (const float*)d_in[6];
    const float* bq  = (const float*)d_in[7];
    const float* Wg  = (const float*)d_in[8];
    const float* bg  = (const float*)d_in[9];
    const float* Wc1 = (const float*)d_in[10];
    const float* bc1 = (const float*)d_in[11];
    const float* Wc2 = (const float*)d_in[12];
    const float* bc2 = (const float*)d_in[13];
    const float* Wo  = (const float*)d_in[14];
    const float* bo  = (const float*)d_in[15];
    const float* mixl = (const float*)d_in[18];
    float* out = (float*)d_out;

    cudaFuncSetAttribute(miras_main, cudaFuncAttributeMaxDynamicSharedMemorySize, SMEM_BYTES);

    prep_keys<<<1, 256>>>(fk, dk);
    miras_main<<<1024, 256, SMEM_BYTES>>>(query, context, fv, dv,
                                          Wq, bq, Wg, bg, Wc1, bc1, Wc2, bc2,
                                          Wo, bo, mixl, out);
}

// round 5
// speedup vs baseline: 1.0001x; 1.0001x over previous
#include <cuda_runtime.h>

typedef unsigned long long u64;

#define Dd   256
#define Hh   4
#define HDh  64
#define Ss   64
#define BM   64
#define TBS  258   // tbuf row stride (floats)
#define ASTR 36    // A staging row stride
#define BSTR 132   // B staging row stride
#define KVSTR 68   // key/val staging row stride
#define SIMSTR 66  // sim buffer row stride

// smem float offsets (BM=64 layout, 114,944 B -> 2 CTAs/SM)
#define OFF_TBUF 0                       // 64*258 = 16512
#define OFF_AS   16512                   // 64*36  = 2304
#define OFF_BS   (16512+2304)            // 32*132 = 4224 ; end 23040
#define OFF_SIM  16512                   // 64*66 = 4224, overlaps As+Bs (attention phase only)
#define OFF_KV   23040                   // 64*68 = 4352 ; end 27392
#define OFF_RED  23040                   // 64*16 = 1024, overlaps kv (phase A only)
#define OFF_CST  27392                   // 1024 : bq(256) bg(256) bo(256) bc1(128) wc2(128)
#define OFF_GACC (OFF_CST+1024)          // 28416
#define OFF_CACC (OFF_GACC+64)
#define OFF_A    (OFF_CACC+64)
#define OFF_B2   (OFF_A+64)
#define OFF_RQ   (OFF_B2+64)
#define SMEM_FLOATS (OFF_RQ+64)          // 28736
#define SMEM_BYTES (SMEM_FLOATS*4)       // 114944

// normalized, transposed keys: [tier][h][d*S + s]
__device__ float g_knT[2][Hh][HDh*Ss];

__global__ void prep_keys(const float* __restrict__ fk, const float* __restrict__ dk) {
    int t = threadIdx.x;          // 256 threads = (h,s)
    int h = t / Ss, s = t % Ss;
    const float* srcs[2] = { fk, dk };
    for (int tier = 0; tier < 2; tier++) {
        const float* src = srcs[tier] + (h * Ss + s) * HDh;
        float ssum = 0.f;
        for (int d2 = 0; d2 < HDh; d2++) { float v = src[d2]; ssum += v * v; }
        float r = 1.0f / (sqrtf(ssum) + 1e-8f);
        for (int d2 = 0; d2 < HDh; d2++)
            g_knT[tier][h][d2 * Ss + s] = src[d2] * r;
    }
}

__device__ __forceinline__ u64 pk2(float v) {
    u64 r; asm("mov.b64 %0, {%1,%2};" : "=l"(r) : "f"(v), "f"(v)); return r;
}
__device__ __forceinline__ void fma2(u64& acc, u64 a, u64 b) {
    asm("fma.rn.f32x2 %0, %1, %2, %0;" : "+l"(acc) : "l"(a), "l"(b));
}
__device__ __forceinline__ float2 unp(u64 v) {
    float2 f; asm("mov.b64 {%0,%1}, %2;" : "=f"(f.x), "=f"(f.y) : "l"(v)); return f;
}

// C[64 x 128] = A[64 x 256] @ W[n0..n0+127, 0..255]^T ; acc = 4x4 f32x2 per thread
__device__ __forceinline__ void gemm_256xN(
    const float* __restrict__ Ag, const float* __restrict__ W, int n0,
    float* As, float* Bs, u64 acc[4][4], int tid, int tx, int ty)
{
    #pragma unroll
    for (int i = 0; i < 4; i++)
        #pragma unroll
        for (int j = 0; j < 4; j++) acc[i][j] = 0ull;

    for (int kt = 0; kt < 8; kt++) {
        const int k0 = kt * 32;
        #pragma unroll
        for (int r = 0; r < 2; r++) {          // stage A tile 64x32 (row-major)
            int lin = tid + r * 256;
            int m = lin >> 3, q = lin & 7;
            float4 v = *(const float4*)(Ag + m * Dd + k0 + q * 4);
            *(float4*)(As + m * ASTR + q * 4) = v;
        }
        #pragma unroll
        for (int r = 0; r < 4; r++) {          // stage B tile transposed: Bs[k][n] = W[n0+n][k0+k]
            int lin = tid + r * 256;
            int n = lin >> 3, q = lin & 7;
            float4 v = *(const float4*)(W + (n0 + n) * Dd + k0 + q * 4);
            Bs[(q * 4 + 0) * BSTR + n] = v.x;
            Bs[(q * 4 + 1) * BSTR + n] = v.y;
            Bs[(q * 4 + 2) * BSTR + n] = v.z;
            Bs[(q * 4 + 3) * BSTR + n] = v.w;
        }
        __syncthreads();
        #pragma unroll
        for (int kk = 0; kk < 32; kk += 4) {
            float4 a4[4];
            #pragma unroll
            for (int i = 0; i < 4; i++)
                a4[i] = *(const float4*)(As + (ty * 4 + i) * ASTR + kk);
            #pragma unroll
            for (int u = 0; u < 4; u++) {
                const float* brow = Bs + (kk + u) * BSTR + tx * 8;
                u64 b0 = *(const u64*)(brow + 0);
                u64 b1 = *(const u64*)(brow + 2);
                u64 b2 = *(const u64*)(brow + 4);
                u64 b3 = *(const u64*)(brow + 6);
                #pragma unroll
                for (int i = 0; i < 4; i++) {
                    float av = (u == 0) ? a4[i].x : (u == 1) ? a4[i].y : (u == 2) ? a4[i].z : a4[i].w;
                    u64 aa = pk2(av);
                    fma2(acc[i][0], aa, b0);
                    fma2(acc[i][1], aa, b1);
                    fma2(acc[i][2], aa, b2);
                    fma2(acc[i][3], aa, b3);
                }
            }
        }
        __syncthreads();
    }
}

// C[64 x 64] (+)= A[64 rows, cols acb..acb+63 of Asm] @ kvS[64 x 64]; acc = 4x2 f32x2
__device__ __forceinline__ void gemm_attn(
    const float* __restrict__ Asm, int astride, int acb,
    const float* __restrict__ kvS, u64 acc[4][2], int tx, int ty, bool zero)
{
    if (zero) {
        #pragma unroll
        for (int i = 0; i < 4; i++) { acc[i][0] = 0ull; acc[i][1] = 0ull; }
    }
    #pragma unroll 8
    for (int kk = 0; kk < 64; kk += 2) {
        float2 a2[4];
        #pragma unroll
        for (int i = 0; i < 4; i++)
            a2[i] = *(const float2*)(Asm + (ty * 4 + i) * astride + acb + kk);
        #pragma unroll
        for (int u = 0; u < 2; u++) {
            const float* brow = kvS + (kk + u) * KVSTR + tx * 4;
            u64 b0 = *(const u64*)(brow);
            u64 b1 = *(const u64*)(brow + 2);
            #pragma unroll
            for (int i = 0; i < 4; i++) {
                u64 aa = pk2(u ? a2[i].y : a2[i].x);
                fma2(acc[i][0], aa, b0);
                fma2(acc[i][1], aa, b1);
            }
        }
    }
}

__device__ __forceinline__ void stage_kv(float* kv, const float* __restrict__ src, int tid) {
    #pragma unroll
    for (int r = 0; r < 4; r++) {
        int lin = tid + r * 256;
        int row = lin >> 4, q = lin & 15;
        float4 v = *(const float4*)(src + row * 64 + q * 4);
        *(float4*)(kv + row * KVSTR + q * 4) = v;
    }
}

__device__ __forceinline__ void softmax_row(float* row, float scale) {
    float mx = -1e30f;
    for (int s2 = 0; s2 < 64; s2++) mx = fmaxf(mx, row[s2]);
    float sum = 0.f;
    for (int s2 = 0; s2 < 64; s2++) { float e = __expf(row[s2] - mx); row[s2] = e; sum += e; }
    float inv = scale / sum;
    for (int s2 = 0; s2 < 64; s2++) row[s2] *= inv;
}

__global__ void __launch_bounds__(256, 2) miras_main(
    const float* __restrict__ query, const float* __restrict__ context,
    const float* __restrict__ fvals, const float* __restrict__ dvals,
    const float* __restrict__ Wq, const float* __restrict__ bq,
    const float* __restrict__ Wg, const float* __restrict__ bg,
    const float* __restrict__ Wc1, const float* __restrict__ bc1,
    const float* __restrict__ Wc2, const float* __restrict__ bc2,
    const float* __restrict__ Wo, const float* __restrict__ bo,
    const float* __restrict__ mixl,
    float* __restrict__ out)
{
    extern __shared__ float sm[];
    float* tbuf = sm + OFF_TBUF;
    float* As   = sm + OFF_AS;
    float* Bs   = sm + OFF_BS;
    float* simb = sm + OFF_SIM;
    float* kv   = sm + OFF_KV;
    float* cst  = sm + OFF_CST;
    float* red  = sm + OFF_RED;
    float* gaccS = sm + OFF_GACC;
    float* caccS = sm + OFF_CACC;
    float* aS   = sm + OFF_A;
    float* b2S  = sm + OFF_B2;
    float* rqS  = sm + OFF_RQ;

    const int tid = threadIdx.x;
    const int tx = tid & 15, ty = tid >> 4;
    const int m0 = blockIdx.x * BM;

    // load small constants into smem
    cst[tid]       = bq[tid];
    cst[256 + tid] = bg[tid];
    cst[512 + tid] = bo[tid];
    if (tid < 128) { cst[768 + tid] = bc1[tid]; cst[896 + tid] = Wc2[tid]; }
    const float mix_logit = mixl[0];
    const float bc2v = bc2[0];
    __syncthreads();

    u64 acc[4][4];

    // ---------- Phase A: gate (Wg) + conf (Wc1) from context ----------
    float gpart[4];
    #pragma unroll
    for (int i = 0; i < 4; i++) gpart[i] = 0.f;

    for (int np = 0; np < 2; np++) {
        gemm_256xN(context + (size_t)m0 * Dd, Wg, np * 128, As, Bs, acc, tid, tx, ty);
        #pragma unroll
        for (int i = 0; i < 4; i++) {
            float s = 0.f;
            #pragma unroll
            for (int j = 0; j < 4; j++) {
                float2 v = unp(acc[i][j]);
                int n = np * 128 + tx * 8 + j * 2;
                s += tanhf(v.x + cst[256 + n]) + tanhf(v.y + cst[256 + n + 1]);
            }
            gpart[i] += s;
        }
    }

    gemm_256xN(context + (size_t)m0 * Dd, Wc1, 0, As, Bs, acc, tid, tx, ty);
    float cpart[4];
    #pragma unroll
    for (int i = 0; i < 4; i++) {
        float s = 0.f;
        #pragma unroll
        for (int j = 0; j < 4; j++) {
            float2 v = unp(acc[i][j]);
            int n = tx * 8 + j * 2;
            s += tanhf(v.x + cst[768 + n]) * cst[896 + n]
               + tanhf(v.y + cst[768 + n + 1]) * cst[896 + n + 1];
        }
        cpart[i] = s;
    }

    // deterministic reductions (red overlaps kv region; kv not used until phase C)
    #pragma unroll
    for (int i = 0; i < 4; i++) red[(ty * 4 + i) * 16 + tx] = gpart[i];
    __syncthreads();
    if (tid < 64) {
        float s = 0.f;
        for (int t16 = 0; t16 < 16; t16++) s += red[tid * 16 + t16];
        gaccS[tid] = s;
    }
    __syncthreads();
    #pragma unroll
    for (int i = 0; i < 4; i++) red[(ty * 4 + i) * 16 + tx] = cpart[i];
    __syncthreads();
    if (tid < 64) {
        float s = 0.f;
        for (int t16 = 0; t16 < 16; t16++) s += red[tid * 16 + t16];
        caccS[tid] = s;
        float gate = gaccS[tid] * (1.0f / 256.0f);
        float mixv = 1.0f / (1.0f + __expf(-(mix_logit + gate)));
        float conf = 1.0f / (1.0f + __expf(-(s + bc2v)));
        aS[tid] = mixv * conf;
        b2S[tid] = (1.0f - mixv) * conf;
    }
    __syncthreads();

    // ---------- Phase B: Q = query @ Wq^T + bq -> tbuf ----------
    for (int np = 0; np < 2; np++) {
        gemm_256xN(query + (size_t)m0 * Dd, Wq, np * 128, As, Bs, acc, tid, tx, ty);
        #pragma unroll
        for (int i = 0; i < 4; i++) {
            int row = ty * 4 + i;
            #pragma unroll
            for (int j = 0; j < 4; j++) {
                float2 v = unp(acc[i][j]);
                int n = np * 128 + tx * 8 + j * 2;
                tbuf[row * TBS + n]     = v.x + cst[n];
                tbuf[row * TBS + n + 1] = v.y + cst[n + 1];
            }
        }
        __syncthreads();
    }

    // ---------- Phase C: dual-tier cosine attention, in-place t over Q ----------
    u64 accS[4][2], accT[4][2];
    for (int h = 0; h < Hh; h++) {
        stage_kv(kv, &g_knT[0][h][0], tid);
        if (tid < 64) {
            const float* qr = tbuf + tid * TBS + h * 64;
            float ssum = 0.f;
            for (int d2 = 0; d2 < 64; d2++) { float v = qr[d2]; ssum += v * v; }
            rqS[tid] = 1.0f / (sqrtf(ssum) + 1e-8f);
        }
        __syncthreads();

        // sim fast = Q_h @ knT_f, scaled by 1/(||q||+eps)
        gemm_attn(tbuf, TBS, h * 64, kv, accS, tx, ty, true);
        #pragma unroll
        for (int i = 0; i < 4; i++) {
            float r = rqS[ty * 4 + i];
            float2 v0 = unp(accS[i][0]), v1 = unp(accS[i][1]);
            float* srow = simb + (ty * 4 + i) * SIMSTR + tx * 4;
            srow[0] = v0.x * r; srow[1] = v0.y * r; srow[2] = v1.x * r; srow[3] = v1.y * r;
        }
        __syncthreads();

        stage_kv(kv, fvals + h * Ss * HDh, tid);
        if (tid < 64) softmax_row(simb + tid * SIMSTR, aS[tid]);   // attnF * conf*mix
        __syncthreads();

        gemm_attn(simb, SIMSTR, 0, kv, accT, tx, ty, true);         // t += attnF' @ fvals
        __syncthreads();

        stage_kv(kv, &g_knT[1][h][0], tid);
        __syncthreads();

        gemm_attn(tbuf, TBS, h * 64, kv, accS, tx, ty, true);       // sim deep
        #pragma unroll
        for (int i = 0; i < 4; i++) {
            float r = rqS[ty * 4 + i];
            float2 v0 = unp(accS[i][0]), v1 = unp(accS[i][1]);
            float* srow = simb + (ty * 4 + i) * SIMSTR + tx * 4;
            srow[0] = v0.x * r; srow[1] = v0.y * r; srow[2] = v1.x * r; srow[3] = v1.y * r;
        }
        __syncthreads();

        stage_kv(kv, dvals + h * Ss * HDh, tid);
        if (tid < 64) softmax_row(simb + tid * SIMSTR, b2S[tid]);  // attnD * conf*(1-mix)
        __syncthreads();

        gemm_attn(simb, SIMSTR, 0, kv, accT, tx, ty, false);        // t += attnD' @ dvals

        #pragma unroll
        for (int i = 0; i < 4; i++) {                               // overwrite Q_h with t_h
            float2 v0 = unp(accT[i][0]), v1 = unp(accT[i][1]);
            float* trow = tbuf + (ty * 4 + i) * TBS + h * 64 + tx * 4;
            trow[0] = v0.x; trow[1] = v0.y; trow[2] = v1.x; trow[3] = v1.y;
        }
        __syncthreads();
    }

    // ---------- Phase D: out = t @ Wo^T + bo ----------
    for (int np = 0; np < 2; np++) {
        #pragma unroll
        for (int i = 0; i < 4; i++)
            #pragma unroll
            for (int j = 0; j < 4; j++) acc[i][j] = 0ull;

        for (int kt = 0; kt < 8; kt++) {
            const int k0 = kt * 32;
            #pragma unroll
            for (int r = 0; r < 4; r++) {
                int lin = tid + r * 256;
                int n = lin >> 3, q = lin & 7;
                float4 v = *(const float4*)(Wo + (np * 128 + n) * Dd + k0 + q * 4);
                Bs[(q * 4 + 0) * BSTR + n] = v.x;
                Bs[(q * 4 + 1) * BSTR + n] = v.y;
                Bs[(q * 4 + 2) * BSTR + n] = v.z;
                Bs[(q * 4 + 3) * BSTR + n] = v.w;
            }
            __syncthreads();
            #pragma unroll
            for (int kk = 0; kk < 32; kk += 2) {
                float2 a2[4];
                #pragma unroll
                for (int i = 0; i < 4; i++)
                    a2[i] = *(const float2*)(tbuf + (ty * 4 + i) * TBS + k0 + kk);
                #pragma unroll
                for (int u = 0; u < 2; u++) {
                    const float* brow = Bs + (kk + u) * BSTR + tx * 8;
                    u64 b0 = *(const u64*)(brow + 0);
                    u64 b1 = *(const u64*)(brow + 2);
                    u64 b2 = *(const u64*)(brow + 4);
                    u64 b3 = *(const u64*)(brow + 6);
                    #pragma unroll
                    for (int i = 0; i < 4; i++) {
                        u64 aa = pk2(u ? a2[i].y : a2[i].x);
                        fma2(acc[i][0], aa, b0);
                        fma2(acc[i][1], aa, b1);
                        fma2(acc[i][2], aa, b2);
                        fma2(acc[i][3], aa, b3);
                    }
                }
            }
            __syncthreads();
        }
        #pragma unroll
        for (int i = 0; i < 4; i++) {
            int row = m0 + ty * 4 + i;
            float2 v0 = unp(acc[i][0]), v1 = unp(acc[i][1]);
            float2 v2 = unp(acc[i][2]), v3 = unp(acc[i][3]);
            int n = np * 128 + tx * 8;
            float4 o0 = make_float4(v0.x + cst[512 + n],     v0.y + cst[512 + n + 1],
                                    v1.x + cst[512 + n + 2], v1.y + cst[512 + n + 3]);
            float4 o1 = make_float4(v2.x + cst[512 + n + 4], v2.y + cst[512 + n + 5],
                                    v3.x + cst[512 + n + 6], v3.y + cst[512 + n + 7]);
            *(float4*)(out + (size_t)row * Dd + n)     = o0;
            *(float4*)(out + (size_t)row * Dd + n + 4) = o1;
        }
    }
}

extern "C" void kernel_launch(void* const* d_in, const int* in_sizes, int n_in,
                              void* d_out, int out_size) {
    (void)in_sizes; (void)n_in; (void)out_size;
    const float* query   = (const float*)d_in[0];
    const float* context = (const float*)d_in[1];
    const float* fk  = (const float*)d_in[2];
    const float* fv  = (const float*)d_in[3];
    const float* dk  = (const float*)d_in[4];
    const float* dv  = (const float*)d_in[5];
    const float* Wq  = (const float*)d_in[6];
    const float* bq  = (const float*)d_in[7];
    const float* Wg  = (const float*)d_in[8];
    const float* bg  = (const float*)d_in[9];
    const float* Wc1 = (const float*)d_in[10];
    const float* bc1 = (const float*)d_in[11];
    const float* Wc2 = (const float*)d_in[12];
    const float* bc2 = (const float*)d_in[13];
    const float* Wo  = (const float*)d_in[14];
    const float* bo  = (const float*)d_in[15];
    const float* mixl = (const float*)d_in[18];
    float* out = (float*)d_out;

    cudaFuncSetAttribute(miras_main, cudaFuncAttributeMaxDynamicSharedMemorySize, SMEM_BYTES);

    prep_keys<<<1, 256>>>(fk, dk);
    miras_main<<<1024, 256, SMEM_BYTES>>>(query, context, fv, dv,
                                          Wq, bq, Wg, bg, Wc1, bc1, Wc2, bc2,
                                          Wo, bo, mixl, out);
}

// round 7
// speedup vs baseline: 2.5934x; 2.5931x over previous
#include <cuda_runtime.h>
#include <cuda_bf16.h>

typedef unsigned long long u64;
typedef unsigned int u32;
typedef unsigned short u16;

// ---------------- smem layout (bytes) ----------------
#define QHo   0        // Q/t split hi: 128 rows x 264 bf16 (stride 528B)
#define QLo   67584    // Q/t split lo
#define AHo   135168   // A chunk hi: 128 x 72 bf16 (stride 144B)
#define ALO   153600   // A chunk lo
#define WHo   172032   // W chunk hi: 128 x 72 bf16
#define WLO   190464   // W chunk lo
// attention overlays (inside A region, 4 x 9216 = 36864)
#define KNHo  135168
#define KNLo  144384
#define VTHo  153600
#define VTLo  162816
#define CSTo  208896   // 1024 floats: bq(256) bg(256) bo(256) bc1(128) wc2(128)
#define SMEM_BYTES 212992

// ---------------- prepped global images ----------------
// W images: packed [kc][n][64] bf16 per matrix; bases (elems): Wg=0, Wc1=65536, Wq=98304, Wo=163840
__device__ uint4 g_Wh_img[28672], g_Wl_img[28672];   // 229376 bf16 each
__device__ uint4 g_knh[2][4][512], g_knl[2][4][512]; // normalized keys [s][d] 64x64
__device__ uint4 g_vth[2][4][512], g_vtl[2][4][512]; // values transposed [d][s] 64x64

// ---------------- helpers ----------------
__device__ __forceinline__ void sp2(float x, float y, u32& h, u32& l) {
    __nv_bfloat16 hx = __float2bfloat16(x), hy = __float2bfloat16(y);
    h = (u32)__bfloat16_as_ushort(hx) | ((u32)__bfloat16_as_ushort(hy) << 16);
    __nv_bfloat16 lx = __float2bfloat16(x - __bfloat162float(hx));
    __nv_bfloat16 ly = __float2bfloat16(y - __bfloat162float(hy));
    l = (u32)__bfloat16_as_ushort(lx) | ((u32)__bfloat16_as_ushort(ly) << 16);
}
__device__ __forceinline__ void spw(float v, u16& h, u16& l) {
    __nv_bfloat16 b = __float2bfloat16(v);
    h = __bfloat16_as_ushort(b);
    l = __bfloat16_as_ushort(__float2bfloat16(v - __bfloat162float(b)));
}
__device__ __forceinline__ u32 smaddr(const void* p) {
    u32 a;
    asm("{ .reg .u64 t; cvta.to.shared.u64 t, %1; cvt.u32.u64 %0, t; }" : "=r"(a) : "l"(p));
    return a;
}
__device__ __forceinline__ void ldsm4(u32 a, u32& r0, u32& r1, u32& r2, u32& r3) {
    asm volatile("ldmatrix.sync.aligned.m8n8.x4.shared.b16 {%0,%1,%2,%3}, [%4];"
                 : "=r"(r0), "=r"(r1), "=r"(r2), "=r"(r3) : "r"(a));
}
__device__ __forceinline__ void mmab(float* c, u32 a0, u32 a1, u32 a2, u32 a3, u32 b0, u32 b1) {
    asm volatile(
        "mma.sync.aligned.m16n8k16.row.col.f32.bf16.bf16.f32 "
        "{%0,%1,%2,%3}, {%4,%5,%6,%7}, {%8,%9}, {%0,%1,%2,%3};"
        : "+f"(c[0]), "+f"(c[1]), "+f"(c[2]), "+f"(c[3])
        : "r"(a0), "r"(a1), "r"(a2), "r"(a3), "r"(b0), "r"(b1));
}
__device__ __forceinline__ float tanha(float x) {
    float y; asm("tanh.approx.f32 %0, %1;" : "=f"(y) : "f"(x)); return y;
}

// K=64 chunk GEMM: C[2*NP tiles][4] += A(16 rows) @ B^T, 3-term bf16 split
template<int NP>
__device__ __forceinline__ void gemm_k64(float (*C)[4], u32 aH, u32 aL, u32 bH, u32 bL) {
    #pragma unroll
    for (int kt = 0; kt < 4; kt++) {
        u32 a0, a1, a2, a3, c0, c1, c2, c3;
        ldsm4(aH + kt * 32, a0, a1, a2, a3);
        ldsm4(aL + kt * 32, c0, c1, c2, c3);
        #pragma unroll
        for (int np = 0; np < NP; np++) {
            u32 b0, b1, b2, b3, d0, d1, d2, d3;
            ldsm4(bH + np * 2304 + kt * 32, b0, b1, b2, b3);
            ldsm4(bL + np * 2304 + kt * 32, d0, d1, d2, d3);
            mmab(C[2 * np], a0, a1, a2, a3, b0, b1);
            mmab(C[2 * np], a0, a1, a2, a3, d0, d1);
            mmab(C[2 * np], c0, c1, c2, c3, b0, b1);
            mmab(C[2 * np + 1], a0, a1, a2, a3, b2, b3);
            mmab(C[2 * np + 1], a0, a1, a2, a3, d2, d3);
            mmab(C[2 * np + 1], c0, c1, c2, c3, b2, b3);
        }
    }
}

__device__ __forceinline__ void stageAf32(char* sma, const float* __restrict__ src, int tid) {
    #pragma unroll
    for (int i = tid; i < 2048; i += 256) {
        int r = i >> 4, c4 = i & 15;
        float4 v = *(const float4*)(src + (size_t)r * 256 + c4 * 4);
        u32 h0, l0, h1, l1;
        sp2(v.x, v.y, h0, l0);
        sp2(v.z, v.w, h1, l1);
        char* p = sma + AHo + r * 144 + c4 * 8;
        *(u64*)p = (u64)h0 | ((u64)h1 << 32);
        *(u64*)(p + (ALO - AHo)) = (u64)l0 | ((u64)l1 << 32);
    }
}
__device__ __forceinline__ void stageWc(char* sma, const uint4* __restrict__ sH,
                                        const uint4* __restrict__ sL, int tid) {
    #pragma unroll
    for (int i = tid; i < 1024; i += 256) {
        int r = i >> 3, c = i & 7;
        u32 d = (u32)(r * 9 + c) * 16;
        *(uint4*)(sma + WHo + d) = sH[i];
        *(uint4*)(sma + WLO + d) = sL[i];
    }
}

// ---------------- prep kernels ----------------
__global__ void prep_W(const float* __restrict__ Wq, const float* __restrict__ Wg,
                       const float* __restrict__ Wc1, const float* __restrict__ Wo) {
    int t = blockIdx.x * blockDim.x + threadIdx.x;   // 0..57343
    const float* src; int N; u32 base; int tt;
    if (t < 16384)      { src = Wg;  N = 256; base = 0u;      tt = t; }
    else if (t < 24576) { src = Wc1; N = 128; base = 65536u;  tt = t - 16384; }
    else if (t < 40960) { src = Wq;  N = 256; base = 98304u;  tt = t - 24576; }
    else                { src = Wo;  N = 256; base = 163840u; tt = t - 40960; }
    int n = tt >> 6, c4 = tt & 63;
    int kc = c4 >> 4, kk = (c4 & 15) * 4;
    float4 v = *(const float4*)(src + (size_t)n * 256 + c4 * 4);
    u32 h0, l0, h1, l1;
    sp2(v.x, v.y, h0, l0);
    sp2(v.z, v.w, h1, l1);
    u32 e = base + (u32)(kc * N + n) * 64 + (u32)kk;
    ((u64*)g_Wh_img)[e >> 2] = (u64)h0 | ((u64)h1 << 32);
    ((u64*)g_Wl_img)[e >> 2] = (u64)l0 | ((u64)l1 << 32);
}

__global__ void prep_kv(const float* __restrict__ fk, const float* __restrict__ fv,
                        const float* __restrict__ dk, const float* __restrict__ dv) {
    int t = blockIdx.x * blockDim.x + threadIdx.x;
    if (t >= 512) return;
    int tier = t >> 8, rem = t & 255, h = rem >> 6, s = rem & 63;
    const float* K = (tier ? dk : fk) + (h * 64 + s) * 64;
    const float* V = (tier ? dv : fv) + (h * 64 + s) * 64;
    float ss = 0.f;
    for (int d = 0; d < 64; d++) { float v = K[d]; ss += v * v; }
    float r = 1.0f / (sqrtf(ss) + 1e-8f);
    u16* knh = (u16*)g_knh[tier][h]; u16* knl = (u16*)g_knl[tier][h];
    u16* vth = (u16*)g_vth[tier][h]; u16* vtl = (u16*)g_vtl[tier][h];
    for (int d = 0; d < 64; d++) {
        u16 hh, ll;
        spw(K[d] * r, hh, ll);
        knh[s * 64 + d] = hh; knl[s * 64 + d] = ll;
        spw(V[d], hh, ll);
        vth[d * 64 + s] = hh; vtl[d * 64 + s] = ll;
    }
}

// ---------------- main kernel ----------------
__global__ void __launch_bounds__(256, 1) miras_mma(
    const float* __restrict__ query, const float* __restrict__ context,
    const float* __restrict__ bq, const float* __restrict__ bg,
    const float* __restrict__ bc1, const float* __restrict__ Wc2,
    const float* __restrict__ bc2, const float* __restrict__ bo,
    const float* __restrict__ mixl, float* __restrict__ outp)
{
    extern __shared__ char sma[];
    const u32 sb = smaddr(sma);
    const int tid = threadIdx.x, lane = tid & 31, warp = tid >> 5;
    const int mb = warp * 16;
    const size_t m0 = (size_t)blockIdx.x * 128;
    float* cst = (float*)(sma + CSTo);

    for (int i = tid; i < 256; i += 256) { cst[i] = bq[i]; cst[256 + i] = bg[i]; cst[512 + i] = bo[i]; }
    if (tid < 128) { cst[768 + tid] = bc1[tid]; cst[896 + tid] = Wc2[tid]; }
    const float mixl_v = __ldg(mixl), bc2v = __ldg(bc2);

    // lane-resolved ldmatrix base offsets
    const u32 arow = (u32)(((lane >> 3) & 1) * 8 + (lane & 7));
    const u32 aOffA = (u32)(mb + arow) * 144 + (u32)(lane >> 4) * 16;
    const u32 aOffQ = (u32)(mb + arow) * 528 + (u32)(lane >> 4) * 16;
    const u32 bOff  = (u32)(((lane >> 4) & 1) * 8 + (lane & 7)) * 144 + (u32)((lane >> 3) & 1) * 16;

    // ---------- Phase A: gate (2 halves) + conf ----------
    float ga0 = 0.f, ga1 = 0.f, ca0 = 0.f, ca1 = 0.f;
    #pragma unroll 1
    for (int pass = 0; pass < 3; pass++) {
        float C[16][4];
        #pragma unroll
        for (int t = 0; t < 16; t++) { C[t][0] = C[t][1] = C[t][2] = C[t][3] = 0.f; }
        const int N = (pass == 2) ? 128 : 256;
        const u32 imgBase = (pass == 2) ? 65536u : 0u;
        const int nh = (pass == 1) ? 1 : 0;
        #pragma unroll 1
        for (int kc = 0; kc < 4; kc++) {
            __syncthreads();
            stageAf32(sma, context + m0 * 256 + kc * 64, tid);
            u32 si = (imgBase + (u32)(kc * N + nh * 128) * 64) >> 3;
            stageWc(sma, g_Wh_img + si, g_Wl_img + si, tid);
            __syncthreads();
            gemm_k64<8>(C, sb + AHo + aOffA, sb + ALO + aOffA, sb + WHo + bOff, sb + WLO + bOff);
        }
        if (pass < 2) {
            #pragma unroll
            for (int t = 0; t < 16; t++) {
                int col = pass * 128 + t * 8 + (lane & 3) * 2;
                ga0 += tanha(C[t][0] + cst[256 + col]) + tanha(C[t][1] + cst[256 + col + 1]);
                ga1 += tanha(C[t][2] + cst[256 + col]) + tanha(C[t][3] + cst[256 + col + 1]);
            }
        } else {
            #pragma unroll
            for (int t = 0; t < 16; t++) {
                int col = t * 8 + (lane & 3) * 2;
                ca0 += tanha(C[t][0] + cst[768 + col]) * cst[896 + col]
                     + tanha(C[t][1] + cst[768 + col + 1]) * cst[896 + col + 1];
                ca1 += tanha(C[t][2] + cst[768 + col]) * cst[896 + col]
                     + tanha(C[t][3] + cst[768 + col + 1]) * cst[896 + col + 1];
            }
        }
    }
    ga0 += __shfl_xor_sync(0xffffffffu, ga0, 1); ga0 += __shfl_xor_sync(0xffffffffu, ga0, 2);
    ga1 += __shfl_xor_sync(0xffffffffu, ga1, 1); ga1 += __shfl_xor_sync(0xffffffffu, ga1, 2);
    ca0 += __shfl_xor_sync(0xffffffffu, ca0, 1); ca0 += __shfl_xor_sync(0xffffffffu, ca0, 2);
    ca1 += __shfl_xor_sync(0xffffffffu, ca1, 1); ca1 += __shfl_xor_sync(0xffffffffu, ca1, 2);
    float mix0 = 1.f / (1.f + __expf(-(mixl_v + ga0 * (1.f / 256.f))));
    float mix1 = 1.f / (1.f + __expf(-(mixl_v + ga1 * (1.f / 256.f))));
    float cf0 = 1.f / (1.f + __expf(-(ca0 + bc2v)));
    float cf1 = 1.f / (1.f + __expf(-(ca1 + bc2v)));
    float aF0 = mix0 * cf0, aD0 = (1.f - mix0) * cf0;
    float aF1 = mix1 * cf1, aD1 = (1.f - mix1) * cf1;

    // ---------- Phase B: Q = query @ Wq^T + bq -> QBUF split; per-head norms ----------
    float ssqA[4] = {0.f, 0.f, 0.f, 0.f}, ssqB[4] = {0.f, 0.f, 0.f, 0.f};
    #pragma unroll 1
    for (int half = 0; half < 2; half++) {
        float C[16][4];
        #pragma unroll
        for (int t = 0; t < 16; t++) { C[t][0] = C[t][1] = C[t][2] = C[t][3] = 0.f; }
        #pragma unroll 1
        for (int kc = 0; kc < 4; kc++) {
            __syncthreads();
            stageAf32(sma, query + m0 * 256 + kc * 64, tid);
            u32 si = (98304u + (u32)(kc * 256 + half * 128) * 64) >> 3;
            stageWc(sma, g_Wh_img + si, g_Wl_img + si, tid);
            __syncthreads();
            gemm_k64<8>(C, sb + AHo + aOffA, sb + ALO + aOffA, sb + WHo + bOff, sb + WLO + bOff);
        }
        #pragma unroll
        for (int t = 0; t < 16; t++) {
            int col = half * 128 + t * 8 + (lane & 3) * 2;
            float v0 = C[t][0] + cst[col], v1 = C[t][1] + cst[col + 1];
            float v2 = C[t][2] + cst[col], v3 = C[t][3] + cst[col + 1];
            int hh = (half * 128 + t * 8) >> 6;
            ssqA[hh] += v0 * v0 + v1 * v1;
            ssqB[hh] += v2 * v2 + v3 * v3;
            u32 ph, pl;
            char* p = sma + QHo + (mb + (lane >> 2)) * 528 + col * 2;
            sp2(v0, v1, ph, pl);
            *(u32*)p = ph; *(u32*)(p + (QLo - QHo)) = pl;
            sp2(v2, v3, ph, pl);
            *(u32*)(p + 8 * 528) = ph; *(u32*)(p + 8 * 528 + (QLo - QHo)) = pl;
        }
    }
    float rqA[4], rqB[4];
    #pragma unroll
    for (int hh = 0; hh < 4; hh++) {
        float s = ssqA[hh];
        s += __shfl_xor_sync(0xffffffffu, s, 1); s += __shfl_xor_sync(0xffffffffu, s, 2);
        rqA[hh] = 1.f / (sqrtf(s) + 1e-8f);
        s = ssqB[hh];
        s += __shfl_xor_sync(0xffffffffu, s, 1); s += __shfl_xor_sync(0xffffffffu, s, 2);
        rqB[hh] = 1.f / (sqrtf(s) + 1e-8f);
    }

    // ---------- Phase C: dual-tier cosine attention (per head) ----------
    #pragma unroll 1
    for (int h = 0; h < 4; h++) {
        float rq0 = (h == 0) ? rqA[0] : (h == 1) ? rqA[1] : (h == 2) ? rqA[2] : rqA[3];
        float rq1 = (h == 0) ? rqB[0] : (h == 1) ? rqB[1] : (h == 2) ? rqB[2] : rqB[3];
        float T[8][4];
        #pragma unroll
        for (int t = 0; t < 8; t++) { T[t][0] = T[t][1] = T[t][2] = T[t][3] = 0.f; }

        #pragma unroll 1
        for (int tier = 0; tier < 2; tier++) {
            __syncthreads();
            {
                const uint4* s0 = g_knh[tier][h]; const uint4* s1 = g_knl[tier][h];
                const uint4* s2 = g_vth[tier][h]; const uint4* s3 = g_vtl[tier][h];
                #pragma unroll
                for (int i = tid; i < 512; i += 256) {
                    int r = i >> 3, c = i & 7;
                    u32 d = (u32)(r * 9 + c) * 16;
                    *(uint4*)(sma + KNHo + d) = s0[i];
                    *(uint4*)(sma + KNLo + d) = s1[i];
                    *(uint4*)(sma + VTHo + d) = s2[i];
                    *(uint4*)(sma + VTLo + d) = s3[i];
                }
            }
            __syncthreads();

            // sim = Q_h @ kn^T (3-split), cols = s
            float S[8][4];
            #pragma unroll
            for (int t = 0; t < 8; t++) { S[t][0] = S[t][1] = S[t][2] = S[t][3] = 0.f; }
            gemm_k64<4>(S, sb + QHo + aOffQ + (u32)h * 128, sb + QLo + aOffQ + (u32)h * 128,
                        sb + KNHo + bOff, sb + KNLo + bOff);

            // softmax (rows in thread quads), fold conf*mix scale
            float sc0 = tier ? aD0 : aF0, sc1 = tier ? aD1 : aF1;
            float mx0 = -1e30f, mx1 = -1e30f;
            #pragma unroll
            for (int t = 0; t < 8; t++) {
                S[t][0] *= rq0; S[t][1] *= rq0; S[t][2] *= rq1; S[t][3] *= rq1;
                mx0 = fmaxf(mx0, fmaxf(S[t][0], S[t][1]));
                mx1 = fmaxf(mx1, fmaxf(S[t][2], S[t][3]));
            }
            mx0 = fmaxf(mx0, __shfl_xor_sync(0xffffffffu, mx0, 1));
            mx0 = fmaxf(mx0, __shfl_xor_sync(0xffffffffu, mx0, 2));
            mx1 = fmaxf(mx1, __shfl_xor_sync(0xffffffffu, mx1, 1));
            mx1 = fmaxf(mx1, __shfl_xor_sync(0xffffffffu, mx1, 2));
            float su0 = 0.f, su1 = 0.f;
            #pragma unroll
            for (int t = 0; t < 8; t++) {
                S[t][0] = __expf(S[t][0] - mx0); S[t][1] = __expf(S[t][1] - mx0);
                S[t][2] = __expf(S[t][2] - mx1); S[t][3] = __expf(S[t][3] - mx1);
                su0 += S[t][0] + S[t][1];
                su1 += S[t][2] + S[t][3];
            }
            su0 += __shfl_xor_sync(0xffffffffu, su0, 1); su0 += __shfl_xor_sync(0xffffffffu, su0, 2);
            su1 += __shfl_xor_sync(0xffffffffu, su1, 1); su1 += __shfl_xor_sync(0xffffffffu, su1, 2);
            float iv0 = sc0 / su0, iv1 = sc1 / su1;

            u32 pH[8][2], pL[8][2];
            #pragma unroll
            for (int t = 0; t < 8; t++) {
                sp2(S[t][0] * iv0, S[t][1] * iv0, pH[t][0], pL[t][0]);
                sp2(S[t][2] * iv1, S[t][3] * iv1, pH[t][1], pL[t][1]);
            }

            // t += P @ V (3-split; P fragments from registers)
            #pragma unroll
            for (int kt = 0; kt < 4; kt++) {
                u32 a0 = pH[2 * kt][0], a1 = pH[2 * kt][1], a2 = pH[2 * kt + 1][0], a3 = pH[2 * kt + 1][1];
                u32 c0 = pL[2 * kt][0], c1 = pL[2 * kt][1], c2 = pL[2 * kt + 1][0], c3 = pL[2 * kt + 1][1];
                #pragma unroll
                for (int np = 0; np < 4; np++) {
                    u32 b0, b1, b2, b3, d0, d1, d2, d3;
                    ldsm4(sb + VTHo + bOff + np * 2304 + kt * 32, b0, b1, b2, b3);
                    ldsm4(sb + VTLo + bOff + np * 2304 + kt * 32, d0, d1, d2, d3);
                    mmab(T[2 * np], a0, a1, a2, a3, b0, b1);
                    mmab(T[2 * np], c0, c1, c2, c3, b0, b1);
                    mmab(T[2 * np], a0, a1, a2, a3, d0, d1);
                    mmab(T[2 * np + 1], a0, a1, a2, a3, b2, b3);
                    mmab(T[2 * np + 1], c0, c1, c2, c3, b2, b3);
                    mmab(T[2 * np + 1], a0, a1, a2, a3, d2, d3);
                }
            }
        }

        // write t_h (split) over Q_h in QBUF (warp-row-exclusive)
        #pragma unroll
        for (int t = 0; t < 8; t++) {
            int col = h * 64 + t * 8 + (lane & 3) * 2;
            u32 ph, pl;
            char* p = sma + QHo + (mb + (lane >> 2)) * 528 + col * 2;
            sp2(T[t][0], T[t][1], ph, pl);
            *(u32*)p = ph; *(u32*)(p + (QLo - QHo)) = pl;
            sp2(T[t][2], T[t][3], ph, pl);
            *(u32*)(p + 8 * 528) = ph; *(u32*)(p + 8 * 528 + (QLo - QHo)) = pl;
        }
        __syncwarp();
    }

    // ---------- Phase D: out = t @ Wo^T + bo ----------
    #pragma unroll 1
    for (int half = 0; half < 2; half++) {
        float C[16][4];
        #pragma unroll
        for (int t = 0; t < 16; t++) { C[t][0] = C[t][1] = C[t][2] = C[t][3] = 0.f; }
        #pragma unroll 1
        for (int kc = 0; kc < 4; kc++) {
            __syncthreads();
            u32 si = (163840u + (u32)(kc * 256 + half * 128) * 64) >> 3;
            stageWc(sma, g_Wh_img + si, g_Wl_img + si, tid);
            __syncthreads();
            gemm_k64<8>(C, sb + QHo + aOffQ + (u32)kc * 128, sb + QLo + aOffQ + (u32)kc * 128,
                        sb + WHo + bOff, sb + WLO + bOff);
        }
        #pragma unroll
        for (int t = 0; t < 16; t++) {
            int col = half * 128 + t * 8 + (lane & 3) * 2;
            size_t r0 = m0 + mb + (lane >> 2);
            float2 o0 = make_float2(C[t][0] + cst[512 + col], C[t][1] + cst[512 + col + 1]);
            *(float2*)(outp + r0 * 256 + col) = o0;
            float2 o1 = make_float2(C[t][2] + cst[512 + col], C[t][3] + cst[512 + col + 1]);
            *(float2*)(outp + (r0 + 8) * 256 + col) = o1;
        }
    }
}

extern "C" void kernel_launch(void* const* d_in, const int* in_sizes, int n_in,
                              void* d_out, int out_size) {
    (void)in_sizes; (void)n_in; (void)out_size;
    const float* query   = (const float*)d_in[0];
    const float* context = (const float*)d_in[1];
    const float* fk  = (const float*)d_in[2];
    const float* fv  = (const float*)d_in[3];
    const float* dk  = (const float*)d_in[4];
    const float* dv  = (const float*)d_in[5];
    const float* Wq  = (const float*)d_in[6];
    const float* bq  = (const float*)d_in[7];
    const float* Wg  = (const float*)d_in[8];
    const float* bg  = (const float*)d_in[9];
    const float* Wc1 = (const float*)d_in[10];
    const float* bc1 = (const float*)d_in[11];
    const float* Wc2 = (const float*)d_in[12];
    const float* bc2 = (const float*)d_in[13];
    const float* Wo  = (const float*)d_in[14];
    const float* bo  = (const float*)d_in[15];
    const float* mixl = (const float*)d_in[18];
    float* out = (float*)d_out;

    cudaFuncSetAttribute(miras_mma, cudaFuncAttributeMaxDynamicSharedMemorySize, SMEM_BYTES);

    prep_W<<<224, 256>>>(Wq, Wg, Wc1, Wo);
    prep_kv<<<2, 256>>>(fk, fv, dk, dv);
    miras_mma<<<512, 256, SMEM_BYTES>>>(query, context, bq, bg, bc1, Wc2, bc2, bo, mixl, out);
}

// round 9
// speedup vs baseline: 2.9748x; 1.1471x over previous
#include <cuda_runtime.h>
#include <cuda_bf16.h>

typedef unsigned long long u64;
typedef unsigned int u32;
typedef unsigned short u16;

// ---------------- smem layout (bytes) ----------------
#define QHo   0        // A/Q/t split hi: 128 rows x 264 bf16 (stride 528B)
#define QLo   67584    // lo
#define P0o   135168   // ping buffer (36864): W chunk hi(18432)+lo(18432) / attn tier0 tiles
#define P1o   172032   // pong buffer (36864)
#define CSTo  208896   // 1024 floats: bq(256) bg(256) bo(256) bc1(128) wc2(128)
#define SMEM_BYTES 212992

// ---------------- prepped global images ----------------
// W images packed [kc][n][64] bf16; elem bases: Wg=0, Wc1=65536, Wq=98304, Wo=163840
__device__ uint4 g_Wh_img[28672], g_Wl_img[28672];
__device__ uint4 g_knh[2][4][512], g_knl[2][4][512]; // normalized keys [s][d] 64x64
__device__ uint4 g_vth[2][4][512], g_vtl[2][4][512]; // values transposed [d][s] 64x64

// ---------------- helpers ----------------
__device__ __forceinline__ void sp2(float x, float y, u32& h, u32& l) {
    __nv_bfloat16 hx = __float2bfloat16(x), hy = __float2bfloat16(y);
    h = (u32)__bfloat16_as_ushort(hx) | ((u32)__bfloat16_as_ushort(hy) << 16);
    __nv_bfloat16 lx = __float2bfloat16(x - __bfloat162float(hx));
    __nv_bfloat16 ly = __float2bfloat16(y - __bfloat162float(hy));
    l = (u32)__bfloat16_as_ushort(lx) | ((u32)__bfloat16_as_ushort(ly) << 16);
}
__device__ __forceinline__ void spw(float v, u16& h, u16& l) {
    __nv_bfloat16 b = __float2bfloat16(v);
    h = __bfloat16_as_ushort(b);
    l = __bfloat16_as_ushort(__float2bfloat16(v - __bfloat162float(b)));
}
__device__ __forceinline__ u32 smaddr(const void* p) {
    u32 a;
    asm("{ .reg .u64 t; cvta.to.shared.u64 t, %1; cvt.u32.u64 %0, t; }" : "=r"(a) : "l"(p));
    return a;
}
__device__ __forceinline__ void ldsm4(u32 a, u32& r0, u32& r1, u32& r2, u32& r3) {
    asm volatile("ldmatrix.sync.aligned.m8n8.x4.shared.b16 {%0,%1,%2,%3}, [%4];"
                 : "=r"(r0), "=r"(r1), "=r"(r2), "=r"(r3) : "r"(a));
}
__device__ __forceinline__ void mmab(float* c, u32 a0, u32 a1, u32 a2, u32 a3, u32 b0, u32 b1) {
    asm volatile(
        "mma.sync.aligned.m16n8k16.row.col.f32.bf16.bf16.f32 "
        "{%0,%1,%2,%3}, {%4,%5,%6,%7}, {%8,%9}, {%0,%1,%2,%3};"
        : "+f"(c[0]), "+f"(c[1]), "+f"(c[2]), "+f"(c[3])
        : "r"(a0), "r"(a1), "r"(a2), "r"(a3), "r"(b0), "r"(b1));
}
__device__ __forceinline__ float tanha(float x) {
    float y; asm("tanh.approx.f32 %0, %1;" : "=f"(y) : "f"(x)); return y;
}
#define CPA16(d, s) asm volatile("cp.async.cg.shared.global [%0], [%1], 16;" :: "r"(d), "l"(s) : "memory")
#define COMMIT()    asm volatile("cp.async.commit_group;" ::: "memory")
#define WAITG0()    asm volatile("cp.async.wait_group 0;" ::: "memory")
#define WAITG1()    asm volatile("cp.async.wait_group 1;" ::: "memory")

// prefetch one 128x64 W chunk (hi+lo) into buffer p
// 128 rows x 64 bf16 = 1024 uint4 per plane; dst row stride 144B (8 x 16B data + 16B pad)
__device__ __forceinline__ void prefW(u32 p, const uint4* imgH, const uint4* imgL, u32 baseE, int tid) {
    const uint4* sH = imgH + (baseE >> 3);
    const uint4* sL = imgL + (baseE >> 3);
    #pragma unroll
    for (int i = tid; i < 1024; i += 256) {
        u32 d = p + (u32)(i >> 3) * 144 + (u32)(i & 7) * 16;
        CPA16(d, (const void*)(sH + i));
        CPA16(d + 18432, (const void*)(sL + i));
    }
    COMMIT();
}

// one K=64 stage: C[2*NP][4] += A(16 rows,64 cols) @ B(NP*16 rows,64 cols)^T
template<int NP, int TERMS>
__device__ __forceinline__ void gemm_stage(float (*C)[4], u32 aH, u32 aL, u32 bH, u32 bL) {
    #pragma unroll
    for (int kt = 0; kt < 4; kt++) {
        u32 a0, a1, a2, a3, e0, e1, e2, e3;
        ldsm4(aH + kt * 32, a0, a1, a2, a3);
        if (TERMS == 3) ldsm4(aL + kt * 32, e0, e1, e2, e3);
        #pragma unroll
        for (int np = 0; np < NP; np++) {
            u32 b0, b1, b2, b3, d0, d1, d2, d3;
            ldsm4(bH + np * 2304 + kt * 32, b0, b1, b2, b3);
            ldsm4(bL + np * 2304 + kt * 32, d0, d1, d2, d3);
            mmab(C[2 * np], a0, a1, a2, a3, b0, b1);
            mmab(C[2 * np], a0, a1, a2, a3, d0, d1);
            if (TERMS == 3) mmab(C[2 * np], e0, e1, e2, e3, b0, b1);
            mmab(C[2 * np + 1], a0, a1, a2, a3, b2, b3);
            mmab(C[2 * np + 1], a0, a1, a2, a3, d2, d3);
            if (TERMS == 3) mmab(C[2 * np + 1], e0, e1, e2, e3, b2, b3);
        }
    }
}

// dual-half sweep (N=256): 8 chunks, C[0..15]=half0, C[16..31]=half1; prolog prefetched chunks 0,1
template<int TERMS>
__device__ __forceinline__ void sweep_dual(float (*C)[4], u32 aH0, u32 aL0, u32 bOff,
                                           u32 P0, u32 P1, const uint4* imgH, const uint4* imgL,
                                           u32 baseE, int tid) {
    #pragma unroll 1
    for (int kc = 0; kc < 4; kc++) {
        WAITG1();
        __syncthreads();
        gemm_stage<8, TERMS>(C, aH0 + (u32)kc * 128, aL0 + (u32)kc * 128, P0 + bOff, P0 + 18432 + bOff);
        if (kc < 3) { __syncthreads(); prefW(P0, imgH, imgL, baseE + (u32)(kc * 2 + 2) * 8192, tid); }
        if (kc == 3) { WAITG0(); } else { WAITG1(); }
        __syncthreads();
        gemm_stage<8, TERMS>(C + 16, aH0 + (u32)kc * 128, aL0 + (u32)kc * 128, P1 + bOff, P1 + 18432 + bOff);
        if (kc < 3) { __syncthreads(); prefW(P1, imgH, imgL, baseE + (u32)(kc * 2 + 3) * 8192, tid); }
    }
    __syncthreads();
}

// single-half sweep (N=128): 4 chunks into one C set; prolog prefetched chunks 0,1
template<int TERMS>
__device__ __forceinline__ void sweep_single(float (*C)[4], u32 aH0, u32 aL0, u32 bOff,
                                             u32 P0, u32 P1, const uint4* imgH, const uint4* imgL,
                                             u32 baseE, int tid) {
    #pragma unroll 1
    for (int s = 0; s < 4; s++) {
        if (s == 3) { WAITG0(); } else { WAITG1(); }
        __syncthreads();
        u32 pb = (s & 1) ? P1 : P0;
        gemm_stage<8, TERMS>(C, aH0 + (u32)s * 128, aL0 + (u32)s * 128, pb + bOff, pb + 18432 + bOff);
        if (s < 2) { __syncthreads(); prefW(pb, imgH, imgL, baseE + (u32)(s + 2) * 8192, tid); }
    }
    __syncthreads();
}

// stage fp32 [128x256] -> QBUF split hi/lo (stride 528)
__device__ __forceinline__ void stageQ(char* sma, const float* __restrict__ src, int tid) {
    #pragma unroll 4
    for (int i = tid; i < 8192; i += 256) {
        int r = i >> 6, c4 = i & 63;
        float4 v = *(const float4*)(src + (size_t)r * 256 + c4 * 4);
        u32 h0, l0, h1, l1;
        sp2(v.x, v.y, h0, l0);
        sp2(v.z, v.w, h1, l1);
        char* p = sma + QHo + r * 528 + c4 * 8;
        *(u64*)p = (u64)h0 | ((u64)h1 << 32);
        *(u64*)(p + (QLo - QHo)) = (u64)l0 | ((u64)l1 << 32);
    }
}

// ---------------- prep kernels ----------------
__global__ void prep_W(const float* __restrict__ Wq, const float* __restrict__ Wg,
                       const float* __restrict__ Wc1, const float* __restrict__ Wo) {
    int t = blockIdx.x * blockDim.x + threadIdx.x;   // 0..57343
    const float* src; int N; u32 base; int tt;
    if (t < 16384)      { src = Wg;  N = 256; base = 0u;      tt = t; }
    else if (t < 24576) { src = Wc1; N = 128; base = 65536u;  tt = t - 16384; }
    else if (t < 40960) { src = Wq;  N = 256; base = 98304u;  tt = t - 24576; }
    else                { src = Wo;  N = 256; base = 163840u; tt = t - 40960; }
    int n = tt >> 6, c4 = tt & 63;
    int kc = c4 >> 4, kk = (c4 & 15) * 4;
    float4 v = *(const float4*)(src + (size_t)n * 256 + c4 * 4);
    u32 h0, l0, h1, l1;
    sp2(v.x, v.y, h0, l0);
    sp2(v.z, v.w, h1, l1);
    u32 e = base + (u32)(kc * N + n) * 64 + (u32)kk;
    ((u64*)g_Wh_img)[e >> 2] = (u64)h0 | ((u64)h1 << 32);
    ((u64*)g_Wl_img)[e >> 2] = (u64)l0 | ((u64)l1 << 32);
}

__global__ void prep_kv(const float* __restrict__ fk, const float* __restrict__ fv,
                        const float* __restrict__ dk, const float* __restrict__ dv) {
    int t = blockIdx.x * blockDim.x + threadIdx.x;
    if (t >= 512) return;
    int tier = t >> 8, rem = t & 255, h = rem >> 6, s = rem & 63;
    const float* K = (tier ? dk : fk) + (h * 64 + s) * 64;
    const float* V = (tier ? dv : fv) + (h * 64 + s) * 64;
    float ss = 0.f;
    for (int d = 0; d < 64; d++) { float v = K[d]; ss += v * v; }
    float r = 1.0f / (sqrtf(ss) + 1e-8f);
    u16* knh = (u16*)g_knh[tier][h]; u16* knl = (u16*)g_knl[tier][h];
    u16* vth = (u16*)g_vth[tier][h]; u16* vtl = (u16*)g_vtl[tier][h];
    for (int d = 0; d < 64; d++) {
        u16 hh, ll;
        spw(K[d] * r, hh, ll);
        knh[s * 64 + d] = hh; knl[s * 64 + d] = ll;
        spw(V[d], hh, ll);
        vth[d * 64 + s] = hh; vtl[d * 64 + s] = ll;
    }
}

// ---------------- main kernel ----------------
__global__ void __launch_bounds__(256, 1) miras_mma(
    const float* __restrict__ query, const float* __restrict__ context,
    const float* __restrict__ bq, const float* __restrict__ bg,
    const float* __restrict__ bc1, const float* __restrict__ Wc2,
    const float* __restrict__ bc2, const float* __restrict__ bo,
    const float* __restrict__ mixl, float* __restrict__ outp)
{
    extern __shared__ char sma[];
    const u32 sb = smaddr(sma);
    const int tid = threadIdx.x, lane = tid & 31, warp = tid >> 5;
    const int mb = warp * 16;
    const size_t m0 = (size_t)blockIdx.x * 128;
    float* cst = (float*)(sma + CSTo);
    const u32 P0 = sb + P0o, P1 = sb + P1o;

    { int i = tid; cst[i] = bq[i]; cst[256 + i] = bg[i]; cst[512 + i] = bo[i]; }
    if (tid < 128) { cst[768 + tid] = bc1[tid]; cst[896 + tid] = Wc2[tid]; }
    const float mixl_v = __ldg(mixl), bc2v = __ldg(bc2);

    // lane-resolved ldmatrix offsets
    const u32 arow = (u32)(((lane >> 3) & 1) * 8 + (lane & 7));
    const u32 aOffQ = (u32)(mb + arow) * 528 + (u32)(lane >> 4) * 16;
    const u32 bOff  = (u32)(((lane >> 4) & 1) * 8 + (lane & 7)) * 144 + (u32)((lane >> 3) & 1) * 16;
    const u32 qH0 = sb + QHo + aOffQ, qL0 = sb + QLo + aOffQ;

    float C[32][4];

    // ---------- Phase A: gate (N=256, 2-term) ----------
    prefW(P0, g_Wh_img, g_Wl_img, 0u, tid);
    prefW(P1, g_Wh_img, g_Wl_img, 8192u, tid);
    stageQ(sma, context + m0 * 256, tid);
    #pragma unroll
    for (int t = 0; t < 32; t++) { C[t][0] = C[t][1] = C[t][2] = C[t][3] = 0.f; }
    sweep_dual<2>(C, qH0, qL0, bOff, P0, P1, g_Wh_img, g_Wl_img, 0u, tid);

    float ga0 = 0.f, ga1 = 0.f;
    #pragma unroll
    for (int t = 0; t < 32; t++) {
        int col = (t >> 4) * 128 + (t & 15) * 8 + (lane & 3) * 2;
        ga0 += tanha(C[t][0] + cst[256 + col]) + tanha(C[t][1] + cst[256 + col + 1]);
        ga1 += tanha(C[t][2] + cst[256 + col]) + tanha(C[t][3] + cst[256 + col + 1]);
    }

    // ---------- conf (N=128, 3-term) ----------
    prefW(P0, g_Wh_img, g_Wl_img, 65536u, tid);
    prefW(P1, g_Wh_img, g_Wl_img, 65536u + 8192u, tid);
    #pragma unroll
    for (int t = 0; t < 16; t++) { C[t][0] = C[t][1] = C[t][2] = C[t][3] = 0.f; }
    sweep_single<3>(C, qH0, qL0, bOff, P0, P1, g_Wh_img, g_Wl_img, 65536u, tid);

    float ca0 = 0.f, ca1 = 0.f;
    #pragma unroll
    for (int t = 0; t < 16; t++) {
        int col = t * 8 + (lane & 3) * 2;
        ca0 += tanha(C[t][0] + cst[768 + col]) * cst[896 + col]
             + tanha(C[t][1] + cst[768 + col + 1]) * cst[896 + col + 1];
        ca1 += tanha(C[t][2] + cst[768 + col]) * cst[896 + col]
             + tanha(C[t][3] + cst[768 + col + 1]) * cst[896 + col + 1];
    }
    ga0 += __shfl_xor_sync(0xffffffffu, ga0, 1); ga0 += __shfl_xor_sync(0xffffffffu, ga0, 2);
    ga1 += __shfl_xor_sync(0xffffffffu, ga1, 1); ga1 += __shfl_xor_sync(0xffffffffu, ga1, 2);
    ca0 += __shfl_xor_sync(0xffffffffu, ca0, 1); ca0 += __shfl_xor_sync(0xffffffffu, ca0, 2);
    ca1 += __shfl_xor_sync(0xffffffffu, ca1, 1); ca1 += __shfl_xor_sync(0xffffffffu, ca1, 2);
    float mix0 = 1.f / (1.f + __expf(-(mixl_v + ga0 * (1.f / 256.f))));
    float mix1 = 1.f / (1.f + __expf(-(mixl_v + ga1 * (1.f / 256.f))));
    float cf0 = 1.f / (1.f + __expf(-(ca0 + bc2v)));
    float cf1 = 1.f / (1.f + __expf(-(ca1 + bc2v)));
    float aF0 = mix0 * cf0, aD0 = (1.f - mix0) * cf0;
    float aF1 = mix1 * cf1, aD1 = (1.f - mix1) * cf1;

    // ---------- Phase B: Q = query @ Wq^T + bq (N=256, 3-term) ----------
    prefW(P0, g_Wh_img, g_Wl_img, 98304u, tid);
    prefW(P1, g_Wh_img, g_Wl_img, 98304u + 8192u, tid);
    stageQ(sma, query + m0 * 256, tid);          // safe: conf sweep ended with __syncthreads
    #pragma unroll
    for (int t = 0; t < 32; t++) { C[t][0] = C[t][1] = C[t][2] = C[t][3] = 0.f; }
    sweep_dual<3>(C, qH0, qL0, bOff, P0, P1, g_Wh_img, g_Wl_img, 98304u, tid);

    // epilogue: +bq, per-head norms, write Q split over QBUF (own rows only)
    float ssqA[4] = {0.f, 0.f, 0.f, 0.f}, ssqB[4] = {0.f, 0.f, 0.f, 0.f};
    #pragma unroll
    for (int t = 0; t < 32; t++) {
        int col = (t >> 4) * 128 + (t & 15) * 8 + (lane & 3) * 2;
        float v0 = C[t][0] + cst[col], v1 = C[t][1] + cst[col + 1];
        float v2 = C[t][2] + cst[col], v3 = C[t][3] + cst[col + 1];
        int hh = col >> 6;
        ssqA[hh] += v0 * v0 + v1 * v1;
        ssqB[hh] += v2 * v2 + v3 * v3;
        u32 ph, pl;
        char* p = sma + QHo + (mb + (lane >> 2)) * 528 + col * 2;
        sp2(v0, v1, ph, pl);
        *(u32*)p = ph; *(u32*)(p + (QLo - QHo)) = pl;
        sp2(v2, v3, ph, pl);
        *(u32*)(p + 8 * 528) = ph; *(u32*)(p + 8 * 528 + (QLo - QHo)) = pl;
    }
    float rqA[4], rqB[4];
    #pragma unroll
    for (int hh = 0; hh < 4; hh++) {
        float s = ssqA[hh];
        s += __shfl_xor_sync(0xffffffffu, s, 1); s += __shfl_xor_sync(0xffffffffu, s, 2);
        rqA[hh] = 1.f / (sqrtf(s) + 1e-8f);
        s = ssqB[hh];
        s += __shfl_xor_sync(0xffffffffu, s, 1); s += __shfl_xor_sync(0xffffffffu, s, 2);
        rqB[hh] = 1.f / (sqrtf(s) + 1e-8f);
    }
    __syncthreads();

    // ---------- Phase C: dual-tier cosine attention ----------
    #pragma unroll 1
    for (int h = 0; h < 4; h++) {
        __syncthreads();   // all warps done with previous head's kv tiles
        {
            const uint4* s0 = g_knh[0][h]; const uint4* s1 = g_knl[0][h];
            const uint4* s2 = g_vth[0][h]; const uint4* s3 = g_vtl[0][h];
            const uint4* s4 = g_knh[1][h]; const uint4* s5 = g_knl[1][h];
            const uint4* s6 = g_vth[1][h]; const uint4* s7 = g_vtl[1][h];
            #pragma unroll
            for (int i = tid; i < 512; i += 256) {
                u32 d = (u32)(i >> 3) * 144 + (u32)(i & 7) * 16;
                CPA16(P0 + d,         (const void*)(s0 + i));
                CPA16(P0 + 9216 + d,  (const void*)(s1 + i));
                CPA16(P0 + 18432 + d, (const void*)(s2 + i));
                CPA16(P0 + 27648 + d, (const void*)(s3 + i));
                CPA16(P1 + d,         (const void*)(s4 + i));
                CPA16(P1 + 9216 + d,  (const void*)(s5 + i));
                CPA16(P1 + 18432 + d, (const void*)(s6 + i));
                CPA16(P1 + 27648 + d, (const void*)(s7 + i));
            }
            COMMIT();
            WAITG0();
        }
        __syncthreads();

        float rq0 = (h == 0) ? rqA[0] : (h == 1) ? rqA[1] : (h == 2) ? rqA[2] : rqA[3];
        float rq1 = (h == 0) ? rqB[0] : (h == 1) ? rqB[1] : (h == 2) ? rqB[2] : rqB[3];
        float T[8][4];
        #pragma unroll
        for (int t = 0; t < 8; t++) { T[t][0] = T[t][1] = T[t][2] = T[t][3] = 0.f; }

        #pragma unroll 1
        for (int tier = 0; tier < 2; tier++) {
            u32 Pt = tier ? P1 : P0;
            // sim = Q_h @ kn^T (3-term)
            float S[8][4];
            #pragma unroll
            for (int t = 0; t < 8; t++) { S[t][0] = S[t][1] = S[t][2] = S[t][3] = 0.f; }
            gemm_stage<4, 3>(S, qH0 + (u32)h * 128, qL0 + (u32)h * 128,
                             Pt + bOff, Pt + 9216 + bOff);

            float sc0 = tier ? aD0 : aF0, sc1 = tier ? aD1 : aF1;
            float mx0 = -1e30f, mx1 = -1e30f;
            #pragma unroll
            for (int t = 0; t < 8; t++) {
                S[t][0] *= rq0; S[t][1] *= rq0; S[t][2] *= rq1; S[t][3] *= rq1;
                mx0 = fmaxf(mx0, fmaxf(S[t][0], S[t][1]));
                mx1 = fmaxf(mx1, fmaxf(S[t][2], S[t][3]));
            }
            mx0 = fmaxf(mx0, __shfl_xor_sync(0xffffffffu, mx0, 1));
            mx0 = fmaxf(mx0, __shfl_xor_sync(0xffffffffu, mx0, 2));
            mx1 = fmaxf(mx1, __shfl_xor_sync(0xffffffffu, mx1, 1));
            mx1 = fmaxf(mx1, __shfl_xor_sync(0xffffffffu, mx1, 2));
            float su0 = 0.f, su1 = 0.f;
            #pragma unroll
            for (int t = 0; t < 8; t++) {
                S[t][0] = __expf(S[t][0] - mx0); S[t][1] = __expf(S[t][1] - mx0);
                S[t][2] = __expf(S[t][2] - mx1); S[t][3] = __expf(S[t][3] - mx1);
                su0 += S[t][0] + S[t][1];
                su1 += S[t][2] + S[t][3];
            }
            su0 += __shfl_xor_sync(0xffffffffu, su0, 1); su0 += __shfl_xor_sync(0xffffffffu, su0, 2);
            su1 += __shfl_xor_sync(0xffffffffu, su1, 1); su1 += __shfl_xor_sync(0xffffffffu, su1, 2);
            float iv0 = sc0 / su0, iv1 = sc1 / su1;

            u32 pH[8][2], pL[8][2];
            #pragma unroll
            for (int t = 0; t < 8; t++) {
                sp2(S[t][0] * iv0, S[t][1] * iv0, pH[t][0], pL[t][0]);
                sp2(S[t][2] * iv1, S[t][3] * iv1, pH[t][1], pL[t][1]);
            }

            // T += P @ V (3-term; P fragments in registers)
            #pragma unroll
            for (int kt = 0; kt < 4; kt++) {
                u32 a0 = pH[2*kt][0], a1 = pH[2*kt][1], a2 = pH[2*kt+1][0], a3 = pH[2*kt+1][1];
                u32 c0 = pL[2*kt][0], c1 = pL[2*kt][1], c2 = pL[2*kt+1][0], c3 = pL[2*kt+1][1];
                #pragma unroll
                for (int np = 0; np < 4; np++) {
                    u32 b0, b1, b2, b3, d0, d1, d2, d3;
                    ldsm4(Pt + 18432 + bOff + np * 2304 + kt * 32, b0, b1, b2, b3);
                    ldsm4(Pt + 27648 + bOff + np * 2304 + kt * 32, d0, d1, d2, d3);
                    mmab(T[2*np],   a0, a1, a2, a3, b0, b1);
                    mmab(T[2*np],   c0, c1, c2, c3, b0, b1);
                    mmab(T[2*np],   a0, a1, a2, a3, d0, d1);
                    mmab(T[2*np+1], a0, a1, a2, a3, b2, b3);
                    mmab(T[2*np+1], c0, c1, c2, c3, b2, b3);
                    mmab(T[2*np+1], a0, a1, a2, a3, d2, d3);
                }
            }
        }

        // write t_h (split) over Q_h in QBUF (own rows only)
        #pragma unroll
        for (int t = 0; t < 8; t++) {
            int col = h * 64 + t * 8 + (lane & 3) * 2;
            u32 ph, pl;
            char* p = sma + QHo + (mb + (lane >> 2)) * 528 + col * 2;
            sp2(T[t][0], T[t][1], ph, pl);
            *(u32*)p = ph; *(u32*)(p + (QLo - QHo)) = pl;
            sp2(T[t][2], T[t][3], ph, pl);
            *(u32*)(p + 8 * 528) = ph; *(u32*)(p + 8 * 528 + (QLo - QHo)) = pl;
        }
        __syncwarp();
    }
    __syncthreads();

    // ---------- Phase D: out = t @ Wo^T + bo (N=256, 3-term) ----------
    prefW(P0, g_Wh_img, g_Wl_img, 163840u, tid);
    prefW(P1, g_Wh_img, g_Wl_img, 163840u + 8192u, tid);
    #pragma unroll
    for (int t = 0; t < 32; t++) { C[t][0] = C[t][1] = C[t][2] = C[t][3] = 0.f; }
    sweep_dual<3>(C, qH0, qL0, bOff, P0, P1, g_Wh_img, g_Wl_img, 163840u, tid);

    #pragma unroll
    for (int t = 0; t < 32; t++) {
        int col = (t >> 4) * 128 + (t & 15) * 8 + (lane & 3) * 2;
        size_t r0 = m0 + mb + (lane >> 2);
        float2 o0 = make_float2(C[t][0] + cst[512 + col], C[t][1] + cst[512 + col + 1]);
        *(float2*)(outp + r0 * 256 + col) = o0;
        float2 o1 = make_float2(C[t][2] + cst[512 + col], C[t][3] + cst[512 + col + 1]);
        *(float2*)(outp + (r0 + 8) * 256 + col) = o1;
    }
}

extern "C" void kernel_launch(void* const* d_in, const int* in_sizes, int n_in,
                              void* d_out, int out_size) {
    (void)in_sizes; (void)n_in; (void)out_size;
    const float* query   = (const float*)d_in[0];
    const float* context = (const float*)d_in[1];
    const float* fk  = (const float*)d_in[2];
    const float* fv  = (const float*)d_in[3];
    const float* dk  = (const float*)d_in[4];
    const float* dv  = (const float*)d_in[5];
    const float* Wq  = (const float*)d_in[6];
    const float* bq  = (const float*)d_in[7];
    const float* Wg  = (const float*)d_in[8];
    const float* bg  = (const float*)d_in[9];
    const float* Wc1 = (const float*)d_in[10];
    const float* bc1 = (const float*)d_in[11];
    const float* Wc2 = (const float*)d_in[12];
    const float* bc2 = (const float*)d_in[13];
    const float* Wo  = (const float*)d_in[14];
    const float* bo  = (const float*)d_in[15];
    const float* mixl = (const float*)d_in[18];
    float* out = (float*)d_out;

    cudaFuncSetAttribute(miras_mma, cudaFuncAttributeMaxDynamicSharedMemorySize, SMEM_BYTES);

    prep_W<<<224, 256>>>(Wq, Wg, Wc1, Wo);
    prep_kv<<<2, 256>>>(fk, fv, dk, dv);
    miras_mma<<<512, 256, SMEM_BYTES>>>(query, context, bq, bg, bc1, Wc2, bc2, bo, mixl, out);
}